// round 16
// baseline (speedup 1.0000x reference)
#include <cuda_runtime.h>
#include <cuda_bf16.h>
#include <math.h>
#include <stdint.h>

// Problem constants
#define B 8
#define N 2048
#define D 384
#define TWO_D 768
#define KNN_K 8
#define BN_ROWS (B * N)      // 16384
#define EPS 1e-5f
#define NEG_SLOPE 0.2f

// ---------------- scratch (device globals; no allocation allowed) -----------
__device__ float g_Y[BN_ROWS * TWO_D];               // GEMM1 out (fp32)
__device__ __nv_bfloat16 g_Xh[BN_ROWS * D];          // x hi/lo split
__device__ __nv_bfloat16 g_Xl[BN_ROWS * D];
__device__ __nv_bfloat16 g_Hh[BN_ROWS * D];          // gather_max out hi/lo
__device__ __nv_bfloat16 g_Hl[BN_ROWS * D];
__device__ __nv_bfloat16 g_W1Bh[TWO_D * D];          // folded w1, [n_out][k]
__device__ __nv_bfloat16 g_W1Bl[TWO_D * D];
__device__ __nv_bfloat16 g_W2h[D * D];               // w2 as-is [n_out][k]
__device__ __nv_bfloat16 g_W2l[D * D];
__device__ int g_idx[BN_ROWS * KNN_K];               // knn indices
__device__ float g_s1[D], g_t1[D], g_s2[D], g_t2[D]; // BN scale/shift

// ======================= helpers ============================================
__device__ __forceinline__ uint32_t smem_u32(const void* p) {
    uint32_t a;
    asm("{ .reg .u64 t; cvta.to.shared.u64 t, %1; cvt.u32.u64 %0, t; }"
        : "=r"(a) : "l"(p));
    return a;
}

#define CP_ASYNC16(smem, gptr) \
    asm volatile("cp.async.cg.shared.global [%0], [%1], 16;" \
        :: "r"(smem), "l"(gptr) : "memory")
#define CP_COMMIT() asm volatile("cp.async.commit_group;" ::: "memory")
#define CP_WAIT(n)  asm volatile("cp.async.wait_group %0;" :: "n"(n) : "memory")

#define LDSM_X4(r, addr) \
    asm volatile("ldmatrix.sync.aligned.m8n8.x4.shared.b16 {%0,%1,%2,%3}, [%4];" \
        : "=r"((r)[0]), "=r"((r)[1]), "=r"((r)[2]), "=r"((r)[3]) : "r"(addr))

#define MMA_BF16(d, a, b0, b1) \
    asm volatile("mma.sync.aligned.m16n8k16.row.col.f32.bf16.bf16.f32 " \
        "{%0,%1,%2,%3}, {%4,%5,%6,%7}, {%8,%9}, {%0,%1,%2,%3};" \
        : "+f"((d)[0]), "+f"((d)[1]), "+f"((d)[2]), "+f"((d)[3]) \
        : "r"((a)[0]), "r"((a)[1]), "r"((a)[2]), "r"((a)[3]), "r"(b0), "r"(b1))

__device__ __forceinline__ void bf16split(float x, __nv_bfloat16& h, __nv_bfloat16& l) {
    h = __float2bfloat16_rn(x);
    l = __float2bfloat16_rn(x - __bfloat162float(h));
}

// ---------------- prep kernels ----------------------------------------------
__global__ void bn_prep_kernel(const float* __restrict__ g1, const float* __restrict__ b1,
                               const float* __restrict__ m1, const float* __restrict__ v1,
                               const float* __restrict__ g2, const float* __restrict__ b2,
                               const float* __restrict__ m2, const float* __restrict__ v2) {
    int c = threadIdx.x;
    if (c < D) {
        float s = g1[c] * rsqrtf(v1[c] + EPS);
        g_s1[c] = s; g_t1[c] = b1[c] - m1[c] * s;
        float s2 = g2[c] * rsqrtf(v2[c] + EPS);
        g_s2[c] = s2; g_t2[c] = b2[c] - m2[c] * s2;
    }
}

// W1B[j][k]: j<384: w1[j][k]; j>=384: w1[j-384][384+k] - w1[j-384][k]
__global__ void prep_weights_kernel(const float* __restrict__ w1,
                                    const float* __restrict__ w2) {
    int i = blockIdx.x * blockDim.x + threadIdx.x;
    if (i < TWO_D * D) {
        int j = i / D;
        int k = i % D;
        float v;
        if (j < D) v = w1[j * TWO_D + k];
        else       v = w1[(j - D) * TWO_D + D + k] - w1[(j - D) * TWO_D + k];
        bf16split(v, g_W1Bh[i], g_W1Bl[i]);
    }
    if (i < D * D) bf16split(w2[i], g_W2h[i], g_W2l[i]);
}

__global__ void split_x_kernel(const float* __restrict__ x) {
    int i = blockIdx.x * blockDim.x + threadIdx.x;
    if (i < BN_ROWS * D) bf16split(x[i], g_Xh[i], g_Xl[i]);
}

// ---------------- KNN: 8 threads/query, unsorted top-8 + tracked worst ------
// Block = 128 threads = 16 queries x 8 parts. Each part scans a 256-point
// slice with per-part rotation (conflict-free: banks (3i + 15*part) mod 32
// distinct for part 0..7). Selection keeps an UNSORTED top-8 plus (w, p) =
// current worst value and its slot; an insert overwrites slot p then rescans
// the 8 slots for the new worst (~16 slots vs ~30 for sorted insert).
// Part 0 merges the other 7 unsorted lists through the same insert.
#define KNN_TPQ 8
#define KNN_QPB 16
#define KNN_SLICE (N / KNN_TPQ)    // 256

// insert into unsorted top-8 with tracked worst
#define KNN_INS(dd, ii, w, p, dval, jval) do { \
    (dd)[p] = (dval); (ii)[p] = (jval); \
    (w) = (dd)[0]; (p) = 0; \
    _Pragma("unroll") \
    for (int _s = 1; _s < KNN_K; _s++) { \
        if ((dd)[_s] > (w)) { (w) = (dd)[_s]; (p) = _s; } \
    } } while (0)

__global__ void __launch_bounds__(128)
knn_kernel(const float* __restrict__ center) {
    __shared__ float sc[N * 3];                            // 24 KB
    __shared__ float cd[KNN_QPB][KNN_TPQ][KNN_K];          // 4 KB
    __shared__ int   ci[KNN_QPB][KNN_TPQ][KNN_K];          // 4 KB

    int b = blockIdx.y;
    const float* cb = center + (size_t)b * N * 3;
    for (int i = threadIdx.x; i < N * 3; i += 128) sc[i] = cb[i];
    __syncthreads();

    int ql = threadIdx.x >> 3;              // 0..15
    int part = threadIdx.x & 7;             // 0..7
    int q = blockIdx.x * KNN_QPB + ql;

    float qx = sc[q * 3 + 0], qy = sc[q * 3 + 1], qz = sc[q * 3 + 2];

    float bd[KNN_K];
    int   bi[KNN_K];
#pragma unroll
    for (int s = 0; s < KNN_K; s++) { bd[s] = 3.4e38f; bi[s] = 0; }
    float w = 3.4e38f;
    int   p = 7;

    int j0 = part * KNN_SLICE;
    int rot = (part * 37) & (KNN_SLICE - 1);   // bank-decorrelating rotation
    for (int ii = 0; ii < KNN_SLICE; ii++) {
        int j = j0 + ((ii + rot) & (KNN_SLICE - 1));
        float dx = sc[j * 3 + 0] - qx;
        float dy = sc[j * 3 + 1] - qy;
        float dz = sc[j * 3 + 2] - qz;
        float d = dx * dx + dy * dy + dz * dz;
        if (d < w) KNN_INS(bd, bi, w, p, d, j);
    }
#pragma unroll
    for (int s = 0; s < KNN_K; s++) {
        cd[ql][part][s] = bd[s];
        ci[ql][part][s] = bi[s];
    }
    __syncthreads();

    // part 0 merges the other 7 unsorted lists (56 candidates)
    if (part == 0) {
        for (int t = 1; t < KNN_TPQ; t++) {
#pragma unroll
            for (int s = 0; s < KNN_K; s++) {
                float d = cd[ql][t][s];
                if (d < w) KNN_INS(bd, bi, w, p, d, ci[ql][t][s]);
            }
        }
        int base = (b * N + q) * KNN_K;
#pragma unroll
        for (int s = 0; s < KNN_K; s++) g_idx[base + s] = bi[s];
    }
}

// ---------------- bf16x3 mma.sync GEMM (ldmatrix + SW64 swizzle) ------------
// Single __syncthreads per K-chunk: prefetch for stage ch+2 is issued right
// after the barrier (its buffer (ch+2)%3 == (ch-1)%3 was last used by
// compute(ch-1), which every warp finished before reaching this barrier).
#define KC 32
#define TILEB 8192                   // 128 rows * 64B
#define STAGE (4 * TILEB)            // Ah, Al, Bh, Bl = 32768
#define NSTG 3
static const int GEMM_SMEM = NSTG * STAGE;   // 98304

__device__ __forceinline__ uint32_t swoff(int row, int seg) {
    return (uint32_t)(row * 64 + ((seg ^ ((row >> 1) & 3)) << 4));
}

template <bool EPI>
__global__ void __launch_bounds__(512, 2)
bf16x3_gemm_kernel(const __nv_bfloat16* __restrict__ Ah,
                   const __nv_bfloat16* __restrict__ Al,
                   const __nv_bfloat16* __restrict__ Bh,
                   const __nv_bfloat16* __restrict__ Bl,
                   float* __restrict__ C, int Nn) {
    extern __shared__ char dsm[];
    uint32_t sb = smem_u32(dsm);
    int tid = threadIdx.x;
    int lane = tid & 31;
    int wid = tid >> 5;
    int wm = wid >> 2;
    int wn = wid & 3;
    int n0 = blockIdx.x * 128;
    int m0 = blockIdx.y * 128;

    int crow = tid >> 2, cseg = tid & 3;
    uint32_t cdst = swoff(crow, cseg);
    size_t gaoff = (size_t)(m0 + crow) * D + cseg * 8;
    size_t gboff = (size_t)(n0 + crow) * D + cseg * 8;

    int rA0 = wm * 32 + (lane & 15);
    int rA1 = rA0 + 16;
    int kA = (lane >> 4) & 1;
    int rB0 = wn * 32 + (lane & 7) + ((lane & 16) >> 1);
    int rB1 = rB0 + 16;
    int kB = (lane >> 3) & 1;

    float acc[2][4][4];
#pragma unroll
    for (int mt = 0; mt < 2; mt++)
#pragma unroll
        for (int nt = 0; nt < 4; nt++)
#pragma unroll
            for (int q = 0; q < 4; q++) acc[mt][nt][q] = 0.f;

#pragma unroll
    for (int pre = 0; pre < 2; pre++) {
        uint32_t bb = sb + pre * STAGE;
        int k0 = pre * KC;
        CP_ASYNC16(bb + cdst,             Ah + gaoff + k0);
        CP_ASYNC16(bb + TILEB + cdst,     Al + gaoff + k0);
        CP_ASYNC16(bb + 2 * TILEB + cdst, Bh + gboff + k0);
        CP_ASYNC16(bb + 3 * TILEB + cdst, Bl + gboff + k0);
        CP_COMMIT();
    }

    for (int ch = 0; ch < D / KC; ch++) {
        if (ch == D / KC - 1) { CP_WAIT(0); } else { CP_WAIT(1); }
        __syncthreads();

        // prefetch stage ch+2 (buffer free: last touched by compute(ch-1))
        if (ch + 2 < D / KC) {
            uint32_t bb = sb + (uint32_t)((ch + 2) % NSTG) * STAGE;
            int k0 = (ch + 2) * KC;
            CP_ASYNC16(bb + cdst,             Ah + gaoff + k0);
            CP_ASYNC16(bb + TILEB + cdst,     Al + gaoff + k0);
            CP_ASYNC16(bb + 2 * TILEB + cdst, Bh + gboff + k0);
            CP_ASYNC16(bb + 3 * TILEB + cdst, Bl + gboff + k0);
            CP_COMMIT();
        }

        uint32_t base = sb + (uint32_t)(ch % NSTG) * STAGE;
#pragma unroll
        for (int s = 0; s < 2; s++) {
            int segA = 2 * s + kA;
            int segB = 2 * s + kB;
            uint32_t ah[2][4], al[2][4];
            LDSM_X4(ah[0], base + swoff(rA0, segA));
            LDSM_X4(ah[1], base + swoff(rA1, segA));
            LDSM_X4(al[0], base + TILEB + swoff(rA0, segA));
            LDSM_X4(al[1], base + TILEB + swoff(rA1, segA));
#pragma unroll
            for (int p = 0; p < 2; p++) {
                int rB = p ? rB1 : rB0;
                uint32_t bh[4], bl[4];
                LDSM_X4(bh, base + 2 * TILEB + swoff(rB, segB));
                LDSM_X4(bl, base + 3 * TILEB + swoff(rB, segB));
#pragma unroll
                for (int mt = 0; mt < 2; mt++) {
                    MMA_BF16(acc[mt][2 * p],     ah[mt], bh[0], bh[1]);
                    MMA_BF16(acc[mt][2 * p],     ah[mt], bl[0], bl[1]);
                    MMA_BF16(acc[mt][2 * p],     al[mt], bh[0], bh[1]);
                    MMA_BF16(acc[mt][2 * p + 1], ah[mt], bh[2], bh[3]);
                    MMA_BF16(acc[mt][2 * p + 1], ah[mt], bl[2], bl[3]);
                    MMA_BF16(acc[mt][2 * p + 1], al[mt], bh[2], bh[3]);
                }
            }
        }
    }

    int rbase = m0 + wm * 32 + (lane >> 2);
    int cb = n0 + wn * 32 + (lane & 3) * 2;
#pragma unroll
    for (int mt = 0; mt < 2; mt++) {
#pragma unroll
        for (int nt = 0; nt < 4; nt++) {
            int row = rbase + mt * 16;
            int col = cb + nt * 8;
            float2 lo2, hi2;
            if (EPI) {
                float2 s = *(const float2*)&g_s2[col];
                float2 t = *(const float2*)&g_t2[col];
                float v0 = acc[mt][nt][0] * s.x + t.x;
                float v1 = acc[mt][nt][1] * s.y + t.y;
                float v2 = acc[mt][nt][2] * s.x + t.x;
                float v3 = acc[mt][nt][3] * s.y + t.y;
                lo2.x = fmaxf(v0, NEG_SLOPE * v0);
                lo2.y = fmaxf(v1, NEG_SLOPE * v1);
                hi2.x = fmaxf(v2, NEG_SLOPE * v2);
                hi2.y = fmaxf(v3, NEG_SLOPE * v3);
            } else {
                lo2.x = acc[mt][nt][0]; lo2.y = acc[mt][nt][1];
                hi2.x = acc[mt][nt][2]; hi2.y = acc[mt][nt][3];
            }
            *(float2*)(C + (size_t)row * Nn + col) = lo2;
            *(float2*)(C + (size_t)(row + 8) * Nn + col) = hi2;
        }
    }
}

// ---------------- gather + BN1 + LeakyReLU + max over K (float4) ------------
// 96 threads, 4 channels each via LDG.128. Writes H pre-split bf16 hi/lo.
__global__ void gather_max_kernel() {
    int n = blockIdx.x;
    int b = n >> 11;
    int d4 = threadIdx.x;           // 0..95
    int c0 = d4 * 4;

    __shared__ int sidx[KNN_K];
    if (d4 < KNN_K) sidx[d4] = g_idx[n * KNN_K + d4];
    __syncthreads();

    float4 s = *(const float4*)&g_s1[c0];
    float4 t = *(const float4*)&g_t1[c0];
    float4 v = *(const float4*)&g_Y[(size_t)n * TWO_D + D + c0];

    float b0 = -3.4e38f, b1 = -3.4e38f, b2 = -3.4e38f, b3 = -3.4e38f;
#pragma unroll
    for (int k = 0; k < KNN_K; k++) {
        int nb = b * N + sidx[k];
        float4 a = *(const float4*)&g_Y[(size_t)nb * TWO_D + c0];
        float h0 = s.x * (a.x + v.x) + t.x;
        float h1 = s.y * (a.y + v.y) + t.y;
        float h2 = s.z * (a.z + v.z) + t.z;
        float h3 = s.w * (a.w + v.w) + t.w;
        b0 = fmaxf(b0, fmaxf(h0, NEG_SLOPE * h0));
        b1 = fmaxf(b1, fmaxf(h1, NEG_SLOPE * h1));
        b2 = fmaxf(b2, fmaxf(h2, NEG_SLOPE * h2));
        b3 = fmaxf(b3, fmaxf(h3, NEG_SLOPE * h3));
    }
    __nv_bfloat16 hh[4], ll[4];
    bf16split(b0, hh[0], ll[0]);
    bf16split(b1, hh[1], ll[1]);
    bf16split(b2, hh[2], ll[2]);
    bf16split(b3, hh[3], ll[3]);
    *(uint2*)&g_Hh[(size_t)n * D + c0] = *(uint2*)hh;
    *(uint2*)&g_Hl[(size_t)n * D + c0] = *(uint2*)ll;
}

// ---------------- launch ----------------------------------------------------
extern "C" void kernel_launch(void* const* d_in, const int* in_sizes, int n_in,
                              void* d_out, int out_size) {
    const float* x      = (const float*)d_in[0];
    const float* center = (const float*)d_in[1];
    const float* w1     = (const float*)d_in[2];
    const float* w2     = (const float*)d_in[3];
    const float* bn1_g  = (const float*)d_in[4];
    const float* bn1_b  = (const float*)d_in[5];
    const float* bn1_m  = (const float*)d_in[6];
    const float* bn1_v  = (const float*)d_in[7];
    const float* bn2_g  = (const float*)d_in[8];
    const float* bn2_b  = (const float*)d_in[9];
    const float* bn2_m  = (const float*)d_in[10];
    const float* bn2_v  = (const float*)d_in[11];
    float* out = (float*)d_out;

    float* Yp;
    __nv_bfloat16 *Xh, *Xl, *Hh, *Hl, *W1h, *W1l, *W2h, *W2l;
    cudaGetSymbolAddress((void**)&Yp,  g_Y);
    cudaGetSymbolAddress((void**)&Xh,  g_Xh);
    cudaGetSymbolAddress((void**)&Xl,  g_Xl);
    cudaGetSymbolAddress((void**)&Hh,  g_Hh);
    cudaGetSymbolAddress((void**)&Hl,  g_Hl);
    cudaGetSymbolAddress((void**)&W1h, g_W1Bh);
    cudaGetSymbolAddress((void**)&W1l, g_W1Bl);
    cudaGetSymbolAddress((void**)&W2h, g_W2h);
    cudaGetSymbolAddress((void**)&W2l, g_W2l);

    cudaFuncSetAttribute(bf16x3_gemm_kernel<false>,
                         cudaFuncAttributeMaxDynamicSharedMemorySize, GEMM_SMEM);
    cudaFuncSetAttribute(bf16x3_gemm_kernel<true>,
                         cudaFuncAttributeMaxDynamicSharedMemorySize, GEMM_SMEM);

    // 1. prep: BN constants, weights, x split
    bn_prep_kernel<<<1, D>>>(bn1_g, bn1_b, bn1_m, bn1_v,
                             bn2_g, bn2_b, bn2_m, bn2_v);
    prep_weights_kernel<<<(TWO_D * D + 255) / 256, 256>>>(w1, w2);
    split_x_kernel<<<(BN_ROWS * D + 255) / 256, 256>>>(x);

    // 2. KNN: 1024 blocks, 8 threads/query, unsorted top-8 + tracked worst
    knn_kernel<<<dim3(N / KNN_QPB, B), 128>>>(center);

    // 3. GEMM1: Y(16384x768) = X @ W1B^T   (bf16x3, fp32 out)
    bf16x3_gemm_kernel<false><<<dim3(TWO_D / 128, BN_ROWS / 128), 512, GEMM_SMEM>>>(
        Xh, Xl, W1h, W1l, Yp, TWO_D);

    // 4. gather + BN1 + lrelu + max over K -> H (bf16 hi/lo), float4
    gather_max_kernel<<<BN_ROWS, D / 4>>>();

    // 5. GEMM2: out = lrelu(bn2(H @ w2^T)), fused epilogue
    bf16x3_gemm_kernel<true><<<dim3(D / 128, BN_ROWS / 128), 512, GEMM_SMEM>>>(
        Hh, Hl, W2h, W2l, out, D);
}

// round 17
// speedup vs baseline: 1.2660x; 1.2660x over previous
#include <cuda_runtime.h>
#include <cuda_bf16.h>
#include <math.h>
#include <stdint.h>

// Problem constants
#define B 8
#define N 2048
#define D 384
#define TWO_D 768
#define KNN_K 8
#define BN_ROWS (B * N)      // 16384
#define EPS 1e-5f
#define NEG_SLOPE 0.2f

// ---------------- scratch (device globals; no allocation allowed) -----------
__device__ float g_Y[BN_ROWS * TWO_D];               // GEMM1 out (fp32)
__device__ __nv_bfloat16 g_Xh[BN_ROWS * D];          // x hi/lo split
__device__ __nv_bfloat16 g_Xl[BN_ROWS * D];
__device__ __nv_bfloat16 g_Hh[BN_ROWS * D];          // gather_max out hi/lo
__device__ __nv_bfloat16 g_Hl[BN_ROWS * D];
__device__ __nv_bfloat16 g_W1Bh[TWO_D * D];          // folded w1, [n_out][k]
__device__ __nv_bfloat16 g_W1Bl[TWO_D * D];
__device__ __nv_bfloat16 g_W2h[D * D];               // w2 as-is [n_out][k]
__device__ __nv_bfloat16 g_W2l[D * D];
__device__ int g_idx[BN_ROWS * KNN_K];               // knn indices
__device__ float g_s1[D], g_t1[D], g_s2[D], g_t2[D]; // BN scale/shift

// ======================= helpers ============================================
__device__ __forceinline__ uint32_t smem_u32(const void* p) {
    uint32_t a;
    asm("{ .reg .u64 t; cvta.to.shared.u64 t, %1; cvt.u32.u64 %0, t; }"
        : "=r"(a) : "l"(p));
    return a;
}

#define CP_ASYNC16(smem, gptr) \
    asm volatile("cp.async.cg.shared.global [%0], [%1], 16;" \
        :: "r"(smem), "l"(gptr) : "memory")
#define CP_COMMIT() asm volatile("cp.async.commit_group;" ::: "memory")
#define CP_WAIT(n)  asm volatile("cp.async.wait_group %0;" :: "n"(n) : "memory")

#define LDSM_X4(r, addr) \
    asm volatile("ldmatrix.sync.aligned.m8n8.x4.shared.b16 {%0,%1,%2,%3}, [%4];" \
        : "=r"((r)[0]), "=r"((r)[1]), "=r"((r)[2]), "=r"((r)[3]) : "r"(addr))

#define MMA_BF16(d, a, b0, b1) \
    asm volatile("mma.sync.aligned.m16n8k16.row.col.f32.bf16.bf16.f32 " \
        "{%0,%1,%2,%3}, {%4,%5,%6,%7}, {%8,%9}, {%0,%1,%2,%3};" \
        : "+f"((d)[0]), "+f"((d)[1]), "+f"((d)[2]), "+f"((d)[3]) \
        : "r"((a)[0]), "r"((a)[1]), "r"((a)[2]), "r"((a)[3]), "r"(b0), "r"(b1))

__device__ __forceinline__ void bf16split(float x, __nv_bfloat16& h, __nv_bfloat16& l) {
    h = __float2bfloat16_rn(x);
    l = __float2bfloat16_rn(x - __bfloat162float(h));
}

// ---------------- prep kernels ----------------------------------------------
__global__ void bn_prep_kernel(const float* __restrict__ g1, const float* __restrict__ b1,
                               const float* __restrict__ m1, const float* __restrict__ v1,
                               const float* __restrict__ g2, const float* __restrict__ b2,
                               const float* __restrict__ m2, const float* __restrict__ v2) {
    int c = threadIdx.x;
    if (c < D) {
        float s = g1[c] * rsqrtf(v1[c] + EPS);
        g_s1[c] = s; g_t1[c] = b1[c] - m1[c] * s;
        float s2 = g2[c] * rsqrtf(v2[c] + EPS);
        g_s2[c] = s2; g_t2[c] = b2[c] - m2[c] * s2;
    }
}

// W1B[j][k]: j<384: w1[j][k]; j>=384: w1[j-384][384+k] - w1[j-384][k]
__global__ void prep_weights_kernel(const float* __restrict__ w1,
                                    const float* __restrict__ w2) {
    int i = blockIdx.x * blockDim.x + threadIdx.x;
    if (i < TWO_D * D) {
        int j = i / D;
        int k = i % D;
        float v;
        if (j < D) v = w1[j * TWO_D + k];
        else       v = w1[(j - D) * TWO_D + D + k] - w1[(j - D) * TWO_D + k];
        bf16split(v, g_W1Bh[i], g_W1Bl[i]);
    }
    if (i < D * D) bf16split(w2[i], g_W2h[i], g_W2l[i]);
}

__global__ void split_x_kernel(const float* __restrict__ x) {
    int i = blockIdx.x * blockDim.x + threadIdx.x;
    if (i < BN_ROWS * D) bf16split(x[i], g_Xh[i], g_Xl[i]);
}

// ---------------- KNN (R15 proven version): 8 threads/query, rotated -------
// Block = 128 threads = 16 queries x 8 parts. Each part scans a 256-point
// slice with per-part rotation (conflict-free: banks (3i + 15*part) mod 32
// distinct for part 0..7). Sorted partial top-8 lists merged per query.
#define KNN_TPQ 8
#define KNN_QPB 16
#define KNN_SLICE (N / KNN_TPQ)    // 256

__global__ void __launch_bounds__(128)
knn_kernel(const float* __restrict__ center) {
    __shared__ float sc[N * 3];                            // 24 KB
    __shared__ float cd[KNN_QPB][KNN_TPQ][KNN_K];          // 4 KB
    __shared__ int   ci[KNN_QPB][KNN_TPQ][KNN_K];          // 4 KB

    int b = blockIdx.y;
    const float* cb = center + (size_t)b * N * 3;
    for (int i = threadIdx.x; i < N * 3; i += 128) sc[i] = cb[i];
    __syncthreads();

    int ql = threadIdx.x >> 3;              // 0..15
    int part = threadIdx.x & 7;             // 0..7
    int q = blockIdx.x * KNN_QPB + ql;

    float qx = sc[q * 3 + 0], qy = sc[q * 3 + 1], qz = sc[q * 3 + 2];

    float bd[KNN_K];
    int   bi[KNN_K];
#pragma unroll
    for (int s = 0; s < KNN_K; s++) { bd[s] = 3.4e38f; bi[s] = 0; }

    int j0 = part * KNN_SLICE;
    int rot = (part * 37) & (KNN_SLICE - 1);   // bank-decorrelating rotation
    for (int ii = 0; ii < KNN_SLICE; ii++) {
        int j = j0 + ((ii + rot) & (KNN_SLICE - 1));
        float dx = sc[j * 3 + 0] - qx;
        float dy = sc[j * 3 + 1] - qy;
        float dz = sc[j * 3 + 2] - qz;
        float d = dx * dx + dy * dy + dz * dz;
        if (d < bd[KNN_K - 1]) {
            bd[KNN_K - 1] = d; bi[KNN_K - 1] = j;
#pragma unroll
            for (int s = KNN_K - 1; s > 0; s--) {
                if (bd[s] < bd[s - 1]) {
                    float td = bd[s]; bd[s] = bd[s - 1]; bd[s - 1] = td;
                    int   ti = bi[s]; bi[s] = bi[s - 1]; bi[s - 1] = ti;
                }
            }
        }
    }
#pragma unroll
    for (int s = 0; s < KNN_K; s++) {
        cd[ql][part][s] = bd[s];
        ci[ql][part][s] = bi[s];
    }
    __syncthreads();

    // part 0 merges the 8 sorted lists (each ascending -> early exit per list)
    if (part == 0) {
        for (int t = 1; t < KNN_TPQ; t++) {
#pragma unroll
            for (int s = 0; s < KNN_K; s++) {
                float d = cd[ql][t][s];
                if (d >= bd[KNN_K - 1]) break;
                int   i = ci[ql][t][s];
                bd[KNN_K - 1] = d; bi[KNN_K - 1] = i;
#pragma unroll
                for (int u = KNN_K - 1; u > 0; u--) {
                    if (bd[u] < bd[u - 1]) {
                        float td = bd[u]; bd[u] = bd[u - 1]; bd[u - 1] = td;
                        int   ti = bi[u]; bi[u] = bi[u - 1]; bi[u - 1] = ti;
                    }
                }
            }
        }
        int base = (b * N + q) * KNN_K;
#pragma unroll
        for (int s = 0; s < KNN_K; s++) g_idx[base + s] = bi[s];
    }
}

// ---------------- bf16x3 mma.sync GEMM (ldmatrix + SW64 swizzle) ------------
// Single __syncthreads per K-chunk: prefetch for stage ch+2 is issued right
// after the barrier (its buffer (ch+2)%3 == (ch-1)%3 was last used by
// compute(ch-1), which every warp finished before reaching this barrier).
#define KC 32
#define TILEB 8192                   // 128 rows * 64B
#define STAGE (4 * TILEB)            // Ah, Al, Bh, Bl = 32768
#define NSTG 3
static const int GEMM_SMEM = NSTG * STAGE;   // 98304

__device__ __forceinline__ uint32_t swoff(int row, int seg) {
    return (uint32_t)(row * 64 + ((seg ^ ((row >> 1) & 3)) << 4));
}

template <bool EPI>
__global__ void __launch_bounds__(512, 2)
bf16x3_gemm_kernel(const __nv_bfloat16* __restrict__ Ah,
                   const __nv_bfloat16* __restrict__ Al,
                   const __nv_bfloat16* __restrict__ Bh,
                   const __nv_bfloat16* __restrict__ Bl,
                   float* __restrict__ C, int Nn) {
    extern __shared__ char dsm[];
    uint32_t sb = smem_u32(dsm);
    int tid = threadIdx.x;
    int lane = tid & 31;
    int wid = tid >> 5;
    int wm = wid >> 2;
    int wn = wid & 3;
    int n0 = blockIdx.x * 128;
    int m0 = blockIdx.y * 128;

    int crow = tid >> 2, cseg = tid & 3;
    uint32_t cdst = swoff(crow, cseg);
    size_t gaoff = (size_t)(m0 + crow) * D + cseg * 8;
    size_t gboff = (size_t)(n0 + crow) * D + cseg * 8;

    int rA0 = wm * 32 + (lane & 15);
    int rA1 = rA0 + 16;
    int kA = (lane >> 4) & 1;
    int rB0 = wn * 32 + (lane & 7) + ((lane & 16) >> 1);
    int rB1 = rB0 + 16;
    int kB = (lane >> 3) & 1;

    float acc[2][4][4];
#pragma unroll
    for (int mt = 0; mt < 2; mt++)
#pragma unroll
        for (int nt = 0; nt < 4; nt++)
#pragma unroll
            for (int q = 0; q < 4; q++) acc[mt][nt][q] = 0.f;

#pragma unroll
    for (int pre = 0; pre < 2; pre++) {
        uint32_t bb = sb + pre * STAGE;
        int k0 = pre * KC;
        CP_ASYNC16(bb + cdst,             Ah + gaoff + k0);
        CP_ASYNC16(bb + TILEB + cdst,     Al + gaoff + k0);
        CP_ASYNC16(bb + 2 * TILEB + cdst, Bh + gboff + k0);
        CP_ASYNC16(bb + 3 * TILEB + cdst, Bl + gboff + k0);
        CP_COMMIT();
    }

    for (int ch = 0; ch < D / KC; ch++) {
        if (ch == D / KC - 1) { CP_WAIT(0); } else { CP_WAIT(1); }
        __syncthreads();

        // prefetch stage ch+2 (buffer free: last touched by compute(ch-1))
        if (ch + 2 < D / KC) {
            uint32_t bb = sb + (uint32_t)((ch + 2) % NSTG) * STAGE;
            int k0 = (ch + 2) * KC;
            CP_ASYNC16(bb + cdst,             Ah + gaoff + k0);
            CP_ASYNC16(bb + TILEB + cdst,     Al + gaoff + k0);
            CP_ASYNC16(bb + 2 * TILEB + cdst, Bh + gboff + k0);
            CP_ASYNC16(bb + 3 * TILEB + cdst, Bl + gboff + k0);
            CP_COMMIT();
        }

        uint32_t base = sb + (uint32_t)(ch % NSTG) * STAGE;
#pragma unroll
        for (int s = 0; s < 2; s++) {
            int segA = 2 * s + kA;
            int segB = 2 * s + kB;
            uint32_t ah[2][4], al[2][4];
            LDSM_X4(ah[0], base + swoff(rA0, segA));
            LDSM_X4(ah[1], base + swoff(rA1, segA));
            LDSM_X4(al[0], base + TILEB + swoff(rA0, segA));
            LDSM_X4(al[1], base + TILEB + swoff(rA1, segA));
#pragma unroll
            for (int p = 0; p < 2; p++) {
                int rB = p ? rB1 : rB0;
                uint32_t bh[4], bl[4];
                LDSM_X4(bh, base + 2 * TILEB + swoff(rB, segB));
                LDSM_X4(bl, base + 3 * TILEB + swoff(rB, segB));
#pragma unroll
                for (int mt = 0; mt < 2; mt++) {
                    MMA_BF16(acc[mt][2 * p],     ah[mt], bh[0], bh[1]);
                    MMA_BF16(acc[mt][2 * p],     ah[mt], bl[0], bl[1]);
                    MMA_BF16(acc[mt][2 * p],     al[mt], bh[0], bh[1]);
                    MMA_BF16(acc[mt][2 * p + 1], ah[mt], bh[2], bh[3]);
                    MMA_BF16(acc[mt][2 * p + 1], ah[mt], bl[2], bl[3]);
                    MMA_BF16(acc[mt][2 * p + 1], al[mt], bh[2], bh[3]);
                }
            }
        }
    }

    int rbase = m0 + wm * 32 + (lane >> 2);
    int cb = n0 + wn * 32 + (lane & 3) * 2;
#pragma unroll
    for (int mt = 0; mt < 2; mt++) {
#pragma unroll
        for (int nt = 0; nt < 4; nt++) {
            int row = rbase + mt * 16;
            int col = cb + nt * 8;
            float2 lo2, hi2;
            if (EPI) {
                float2 s = *(const float2*)&g_s2[col];
                float2 t = *(const float2*)&g_t2[col];
                float v0 = acc[mt][nt][0] * s.x + t.x;
                float v1 = acc[mt][nt][1] * s.y + t.y;
                float v2 = acc[mt][nt][2] * s.x + t.x;
                float v3 = acc[mt][nt][3] * s.y + t.y;
                lo2.x = fmaxf(v0, NEG_SLOPE * v0);
                lo2.y = fmaxf(v1, NEG_SLOPE * v1);
                hi2.x = fmaxf(v2, NEG_SLOPE * v2);
                hi2.y = fmaxf(v3, NEG_SLOPE * v3);
            } else {
                lo2.x = acc[mt][nt][0]; lo2.y = acc[mt][nt][1];
                hi2.x = acc[mt][nt][2]; hi2.y = acc[mt][nt][3];
            }
            *(float2*)(C + (size_t)row * Nn + col) = lo2;
            *(float2*)(C + (size_t)(row + 8) * Nn + col) = hi2;
        }
    }
}

// ---------------- gather + BN1 + LeakyReLU + max over K (float4) ------------
// 96 threads, 4 channels each via LDG.128. Writes H pre-split bf16 hi/lo.
__global__ void gather_max_kernel() {
    int n = blockIdx.x;
    int b = n >> 11;
    int d4 = threadIdx.x;           // 0..95
    int c0 = d4 * 4;

    __shared__ int sidx[KNN_K];
    if (d4 < KNN_K) sidx[d4] = g_idx[n * KNN_K + d4];
    __syncthreads();

    float4 s = *(const float4*)&g_s1[c0];
    float4 t = *(const float4*)&g_t1[c0];
    float4 v = *(const float4*)&g_Y[(size_t)n * TWO_D + D + c0];

    float b0 = -3.4e38f, b1 = -3.4e38f, b2 = -3.4e38f, b3 = -3.4e38f;
#pragma unroll
    for (int k = 0; k < KNN_K; k++) {
        int nb = b * N + sidx[k];
        float4 a = *(const float4*)&g_Y[(size_t)nb * TWO_D + c0];
        float h0 = s.x * (a.x + v.x) + t.x;
        float h1 = s.y * (a.y + v.y) + t.y;
        float h2 = s.z * (a.z + v.z) + t.z;
        float h3 = s.w * (a.w + v.w) + t.w;
        b0 = fmaxf(b0, fmaxf(h0, NEG_SLOPE * h0));
        b1 = fmaxf(b1, fmaxf(h1, NEG_SLOPE * h1));
        b2 = fmaxf(b2, fmaxf(h2, NEG_SLOPE * h2));
        b3 = fmaxf(b3, fmaxf(h3, NEG_SLOPE * h3));
    }
    __nv_bfloat16 hh[4], ll[4];
    bf16split(b0, hh[0], ll[0]);
    bf16split(b1, hh[1], ll[1]);
    bf16split(b2, hh[2], ll[2]);
    bf16split(b3, hh[3], ll[3]);
    *(uint2*)&g_Hh[(size_t)n * D + c0] = *(uint2*)hh;
    *(uint2*)&g_Hl[(size_t)n * D + c0] = *(uint2*)ll;
}

// ---------------- launch ----------------------------------------------------
extern "C" void kernel_launch(void* const* d_in, const int* in_sizes, int n_in,
                              void* d_out, int out_size) {
    const float* x      = (const float*)d_in[0];
    const float* center = (const float*)d_in[1];
    const float* w1     = (const float*)d_in[2];
    const float* w2     = (const float*)d_in[3];
    const float* bn1_g  = (const float*)d_in[4];
    const float* bn1_b  = (const float*)d_in[5];
    const float* bn1_m  = (const float*)d_in[6];
    const float* bn1_v  = (const float*)d_in[7];
    const float* bn2_g  = (const float*)d_in[8];
    const float* bn2_b  = (const float*)d_in[9];
    const float* bn2_m  = (const float*)d_in[10];
    const float* bn2_v  = (const float*)d_in[11];
    float* out = (float*)d_out;

    float* Yp;
    __nv_bfloat16 *Xh, *Xl, *Hh, *Hl, *W1h, *W1l, *W2h, *W2l;
    cudaGetSymbolAddress((void**)&Yp,  g_Y);
    cudaGetSymbolAddress((void**)&Xh,  g_Xh);
    cudaGetSymbolAddress((void**)&Xl,  g_Xl);
    cudaGetSymbolAddress((void**)&Hh,  g_Hh);
    cudaGetSymbolAddress((void**)&Hl,  g_Hl);
    cudaGetSymbolAddress((void**)&W1h, g_W1Bh);
    cudaGetSymbolAddress((void**)&W1l, g_W1Bl);
    cudaGetSymbolAddress((void**)&W2h, g_W2h);
    cudaGetSymbolAddress((void**)&W2l, g_W2l);

    cudaFuncSetAttribute(bf16x3_gemm_kernel<false>,
                         cudaFuncAttributeMaxDynamicSharedMemorySize, GEMM_SMEM);
    cudaFuncSetAttribute(bf16x3_gemm_kernel<true>,
                         cudaFuncAttributeMaxDynamicSharedMemorySize, GEMM_SMEM);

    // Fork a side stream so knn (center-only dependency) runs concurrently
    // with prep + GEMM1 inside the captured graph. Created per call, never
    // destroyed mid-capture (kernel_launch runs only a handful of times).
    cudaStream_t s2;
    cudaStreamCreate(&s2);
    cudaEvent_t eFork, eJoin;
    cudaEventCreateWithFlags(&eFork, cudaEventDisableTiming);
    cudaEventCreateWithFlags(&eJoin, cudaEventDisableTiming);

    cudaEventRecord(eFork, 0);
    cudaStreamWaitEvent(s2, eFork, 0);

    // side stream: KNN (1024 blocks, 8 threads/query, R15 proven version)
    knn_kernel<<<dim3(N / KNN_QPB, B), 128, 0, s2>>>(center);
    cudaEventRecord(eJoin, s2);

    // main stream: prep + GEMM1 (independent of knn)
    bn_prep_kernel<<<1, D>>>(bn1_g, bn1_b, bn1_m, bn1_v,
                             bn2_g, bn2_b, bn2_m, bn2_v);
    prep_weights_kernel<<<(TWO_D * D + 255) / 256, 256>>>(w1, w2);
    split_x_kernel<<<(BN_ROWS * D + 255) / 256, 256>>>(x);
    bf16x3_gemm_kernel<false><<<dim3(TWO_D / 128, BN_ROWS / 128), 512, GEMM_SMEM>>>(
        Xh, Xl, W1h, W1l, Yp, TWO_D);

    // join: gather needs knn + GEMM1 + bn1 constants
    cudaStreamWaitEvent(0, eJoin, 0);
    gather_max_kernel<<<BN_ROWS, D / 4>>>();

    // GEMM2: out = lrelu(bn2(H @ w2^T)), fused epilogue
    bf16x3_gemm_kernel<true><<<dim3(D / 128, BN_ROWS / 128), 512, GEMM_SMEM>>>(
        Hh, Hl, W2h, W2l, out, D);
}